// round 12
// baseline (speedup 1.0000x reference)
#include <cuda_runtime.h>
#include <cuda_bf16.h>

// ---------------------------------------------------------------------------
// Problem constants
// ---------------------------------------------------------------------------
#define NN 100000
#define EE 1600000
#define DT 768
#define DV 512
#define DE 128
#define NC 40

// ---------------------------------------------------------------------------
// Scratch (device globals — no allocation allowed)
// ---------------------------------------------------------------------------
__device__ float g_et[(size_t)NN * DE];
__device__ float g_ev[(size_t)NN * DE];
__device__ float g_t [(size_t)NN * DE];   // transformed features (pre-aggregation)
__device__ float g_h [(size_t)NN * DE];   // aggregated output
__device__ int   g_deg_in [NN];
__device__ int   g_deg_out[NN];
__device__ int   g_row    [NN];           // CSR row starts (by dst)
__device__ int   g_cursor [NN];
__device__ int   g_bsum   [128];
__device__ float g_inv_in [NN];
__device__ float g_inv_out[NN];
__device__ int   g_csr_src[EE];
__device__ float g_csr_w  [EE];

// ---------------------------------------------------------------------------
// Degree / CSR kernels
// ---------------------------------------------------------------------------
__global__ void zero3_kernel(int n) {
    int i = blockIdx.x * blockDim.x + threadIdx.x;
    if (i < n) { g_deg_in[i] = 0; g_deg_out[i] = 0; g_cursor[i] = 0; }
}

__global__ void hist_kernel(const int* __restrict__ src, const int* __restrict__ dst, int e) {
    int i = blockIdx.x * blockDim.x + threadIdx.x;
    if (i < e) {
        atomicAdd(&g_deg_out[src[i]], 1);
        atomicAdd(&g_deg_in [dst[i]], 1);
    }
}

__global__ void inv_kernel(int n) {
    int i = blockIdx.x * blockDim.x + threadIdx.x;
    if (i < n) {
        int dout = g_deg_out[i]; if (dout < 1) dout = 1;
        int din  = g_deg_in [i]; if (din  < 1) din  = 1;
        g_inv_out[i] = rsqrtf((float)dout);
        g_inv_in [i] = rsqrtf((float)din);
    }
}

// exclusive scan of deg_in -> g_row (3 kernels)
__global__ void scan_local(int n) {
    __shared__ int s[1024];
    int t = threadIdx.x;
    int gid = blockIdx.x * 1024 + t;
    int v = (gid < n) ? g_deg_in[gid] : 0;
    s[t] = v;
    __syncthreads();
    for (int off = 1; off < 1024; off <<= 1) {
        int x = (t >= off) ? s[t - off] : 0;
        __syncthreads();
        s[t] += x;
        __syncthreads();
    }
    if (gid < n) g_row[gid] = s[t] - v;       // local exclusive
    if (t == 1023) g_bsum[blockIdx.x] = s[1023];
}

__global__ void scan_bsums(int nb) {
    if (blockIdx.x == 0 && threadIdx.x == 0) {
        int run = 0;
        for (int i = 0; i < nb; i++) { int v = g_bsum[i]; g_bsum[i] = run; run += v; }
    }
}

__global__ void scan_add(int n) {
    int gid = blockIdx.x * blockDim.x + threadIdx.x;
    if (gid < n) g_row[gid] += g_bsum[gid >> 10];
}

__global__ void scatter_kernel(const int* __restrict__ src, const int* __restrict__ dst, int e) {
    int i = blockIdx.x * blockDim.x + threadIdx.x;
    if (i < e) {
        int s = src[i], d = dst[i];
        int pos = atomicAdd(&g_cursor[d], 1);
        int idx = g_row[d] + pos;
        g_csr_src[idx] = s;
        g_csr_w[idx]   = g_inv_out[s] * g_inv_in[d];
    }
}

// ---------------------------------------------------------------------------
// Tiled SGEMM: C[M x 128] (+)= A[M x K] @ W[K x 128]  (optional bias+relu)
// BM=128, BN=128, BK=8, 256 threads, 8x8 per thread
// ---------------------------------------------------------------------------
template <bool RELU, bool BIAS, bool ACCUM>
__global__ __launch_bounds__(256)
void gemm_n128(const float* __restrict__ A, const float* __restrict__ W,
               const float* __restrict__ bias, float* __restrict__ C,
               int M, int K) {
    __shared__ float As[8][132];
    __shared__ __align__(16) float Ws[8][128];

    int tid = threadIdx.x;
    int rowBase = blockIdx.x * 128;

    int arow = tid >> 1;             // 0..127
    int akq  = (tid & 1) * 4;        // 0 or 4
    int wk   = tid >> 5;             // 0..7
    int wn   = (tid & 31) * 4;       // 0..124

    int tx = tid & 15, ty = tid >> 4;

    float acc[8][8];
#pragma unroll
    for (int i = 0; i < 8; i++)
#pragma unroll
        for (int j = 0; j < 8; j++) acc[i][j] = 0.f;

    const bool arow_ok = (rowBase + arow) < M;
    const float* Aptr = A + (size_t)(rowBase + arow) * K;

    for (int k0 = 0; k0 < K; k0 += 8) {
        float4 av = arow_ok ? *(const float4*)(Aptr + k0 + akq) : make_float4(0.f, 0.f, 0.f, 0.f);
        float4 wv = *(const float4*)(W + (size_t)(k0 + wk) * 128 + wn);
        __syncthreads();
        As[akq + 0][arow] = av.x;
        As[akq + 1][arow] = av.y;
        As[akq + 2][arow] = av.z;
        As[akq + 3][arow] = av.w;
        *(float4*)&Ws[wk][wn] = wv;
        __syncthreads();
#pragma unroll
        for (int kk = 0; kk < 8; kk++) {
            float a[8], b[8];
#pragma unroll
            for (int i = 0; i < 8; i++) a[i] = As[kk][ty * 8 + i];
#pragma unroll
            for (int j = 0; j < 8; j++) b[j] = Ws[kk][tx * 8 + j];
#pragma unroll
            for (int i = 0; i < 8; i++)
#pragma unroll
                for (int j = 0; j < 8; j++) acc[i][j] += a[i] * b[j];
        }
    }

    float bl[8];
#pragma unroll
    for (int j = 0; j < 8; j++) bl[j] = BIAS ? bias[tx * 8 + j] : 0.f;

#pragma unroll
    for (int i = 0; i < 8; i++) {
        int m = rowBase + ty * 8 + i;
        if (m < M) {
            float* cp = C + (size_t)m * 128 + tx * 8;
            float v[8];
#pragma unroll
            for (int j = 0; j < 8; j++) {
                v[j] = acc[i][j] + bl[j];
            }
            if (ACCUM) {
                float4 o0 = *(float4*)cp;
                float4 o1 = *(float4*)(cp + 4);
                v[0] += o0.x; v[1] += o0.y; v[2] += o0.z; v[3] += o0.w;
                v[4] += o1.x; v[5] += o1.y; v[6] += o1.z; v[7] += o1.w;
            }
            if (RELU) {
#pragma unroll
                for (int j = 0; j < 8; j++) v[j] = fmaxf(v[j], 0.f);
            }
            float4 s0 = make_float4(v[0], v[1], v[2], v[3]);
            float4 s1 = make_float4(v[4], v[5], v[6], v[7]);
            *(float4*)cp = s0;
            *(float4*)(cp + 4) = s1;
        }
    }
}

// ---------------------------------------------------------------------------
// Edge aggregation: out[d] = sum_{e: dst=d} w_e * t[src_e] + bias
// One warp per node; 4 floats per lane -> 128-wide accumulator in registers.
// ---------------------------------------------------------------------------
__global__ void aggregate_kernel(const float* __restrict__ t, const float* __restrict__ bias,
                                 float* __restrict__ out, int n) {
    int warp = (blockIdx.x * blockDim.x + threadIdx.x) >> 5;
    int lane = threadIdx.x & 31;
    if (warp >= n) return;
    int start = g_row[warp];
    int cnt   = g_deg_in[warp];
    const int c = lane * 4;
    float4 acc = make_float4(0.f, 0.f, 0.f, 0.f);
    int i = 0;
    // unroll by 2 for MLP
    for (; i + 1 < cnt; i += 2) {
        int   s0 = g_csr_src[start + i];
        float w0 = g_csr_w  [start + i];
        int   s1 = g_csr_src[start + i + 1];
        float w1 = g_csr_w  [start + i + 1];
        float4 v0 = *(const float4*)(t + (size_t)s0 * 128 + c);
        float4 v1 = *(const float4*)(t + (size_t)s1 * 128 + c);
        acc.x += w0 * v0.x; acc.y += w0 * v0.y; acc.z += w0 * v0.z; acc.w += w0 * v0.w;
        acc.x += w1 * v1.x; acc.y += w1 * v1.y; acc.z += w1 * v1.z; acc.w += w1 * v1.w;
    }
    for (; i < cnt; i++) {
        int   s = g_csr_src[start + i];
        float w = g_csr_w  [start + i];
        float4 v = *(const float4*)(t + (size_t)s * 128 + c);
        acc.x += w * v.x; acc.y += w * v.y; acc.z += w * v.z; acc.w += w * v.w;
    }
    float4 b = *(const float4*)(bias + c);
    acc.x += b.x; acc.y += b.y; acc.z += b.z; acc.w += b.w;
    *(float4*)(out + (size_t)warp * 128 + c) = acc;
}

// ---------------------------------------------------------------------------
// Heads: logits_C = h@Wc+bc ; Ut = et@Wt+bt ; Uv = ev@Wv+bv ; final = avg/3
// One warp per node; lane covers col=lane and (lane<8) col=lane+32.
// Weights staged in dynamic smem (3 * 128*40 floats = 61440 B).
// ---------------------------------------------------------------------------
__global__ void heads_kernel(const float* __restrict__ et, const float* __restrict__ ev,
                             const float* __restrict__ h,
                             const float* __restrict__ Wc, const float* __restrict__ bc,
                             const float* __restrict__ Wt, const float* __restrict__ bt,
                             const float* __restrict__ Wv, const float* __restrict__ bv,
                             float* __restrict__ out, int n) {
    extern __shared__ float sw[];
    float* sWc = sw;
    float* sWt = sw + 5120;
    float* sWv = sw + 10240;
    for (int i = threadIdx.x; i < 5120; i += blockDim.x) {
        sWc[i] = Wc[i]; sWt[i] = Wt[i]; sWv[i] = Wv[i];
    }
    __syncthreads();

    int warp   = (blockIdx.x * blockDim.x + threadIdx.x) >> 5;
    int lane   = threadIdx.x & 31;
    int nwarps = (gridDim.x * blockDim.x) >> 5;
    bool s2 = lane < 8;
    int col1 = lane, col2 = 32 + lane;
    size_t MO = (size_t)n * 40;

    for (int node = warp; node < n; node += nwarps) {
        const float* xt = et + (size_t)node * 128;
        const float* xv = ev + (size_t)node * 128;
        const float* xh = h  + (size_t)node * 128;
        float c0 = 0.f, c1 = 0.f, t0 = 0.f, t1 = 0.f, v0 = 0.f, v1 = 0.f;
#pragma unroll 4
        for (int k = 0; k < 128; k++) {
            float a = xh[k], b = xt[k], c = xv[k];
            c0 += a * sWc[k * 40 + col1];
            t0 += b * sWt[k * 40 + col1];
            v0 += c * sWv[k * 40 + col1];
            if (s2) {
                c1 += a * sWc[k * 40 + col2];
                t1 += b * sWt[k * 40 + col2];
                v1 += c * sWv[k * 40 + col2];
            }
        }
        c0 += bc[col1]; t0 += bt[col1]; v0 += bv[col1];
        float f0 = (c0 + t0 + v0) * (1.f / 3.f);
        size_t base = (size_t)node * 40;
        out[base + col1]          = f0;
        out[MO + base + col1]     = c0;
        out[2 * MO + base + col1] = t0;
        out[3 * MO + base + col1] = v0;
        if (s2) {
            c1 += bc[col2]; t1 += bt[col2]; v1 += bv[col2];
            float f1 = (c1 + t1 + v1) * (1.f / 3.f);
            out[base + col2]          = f1;
            out[MO + base + col2]     = c1;
            out[2 * MO + base + col2] = t1;
            out[3 * MO + base + col2] = v1;
        }
    }
}

// ---------------------------------------------------------------------------
// Launch
// ---------------------------------------------------------------------------
extern "C" void kernel_launch(void* const* d_in, const int* in_sizes, int n_in,
                              void* d_out, int out_size) {
    const float* text = (const float*)d_in[0];
    const float* vis  = (const float*)d_in[1];
    const int* esrc   = (const int*)d_in[2];
    const int* edst   = (const int*)d_in[3];
    const float* W_t  = (const float*)d_in[4];
    const float* b_t  = (const float*)d_in[5];
    const float* W_v  = (const float*)d_in[6];
    const float* b_v  = (const float*)d_in[7];
    const float* W_mp0 = (const float*)d_in[8];
    const float* b_mp0 = (const float*)d_in[9];
    const float* W_mp1 = (const float*)d_in[10];
    const float* b_mp1 = (const float*)d_in[11];
    const float* W_c  = (const float*)d_in[12];
    const float* b_c  = (const float*)d_in[13];
    const float* W_ut = (const float*)d_in[14];
    const float* b_ut = (const float*)d_in[15];
    const float* W_uv = (const float*)d_in[16];
    const float* b_uv = (const float*)d_in[17];
    float* out = (float*)d_out;

    int n = in_sizes[0] / DT;   // 100000
    int e = in_sizes[2];        // 1600000

    float *p_et, *p_ev, *p_t, *p_h;
    cudaGetSymbolAddress((void**)&p_et, g_et);
    cudaGetSymbolAddress((void**)&p_ev, g_ev);
    cudaGetSymbolAddress((void**)&p_t,  g_t);
    cudaGetSymbolAddress((void**)&p_h,  g_h);

    int nb_n = (n + 255) / 256;
    int nb_e = (e + 255) / 256;
    int nb_scan = (n + 1023) / 1024;

    // --- graph prep: degrees, norms, CSR by dst ---
    zero3_kernel<<<nb_n, 256>>>(n);
    hist_kernel<<<nb_e, 256>>>(esrc, edst, e);
    inv_kernel<<<nb_n, 256>>>(n);
    scan_local<<<nb_scan, 1024>>>(n);
    scan_bsums<<<1, 32>>>(nb_scan);
    scan_add<<<nb_n, 256>>>(n);
    scatter_kernel<<<nb_e, 256>>>(esrc, edst, e);

    // --- modality encoders ---
    int gm = (n + 127) / 128;
    gemm_n128<true, true, false><<<gm, 256>>>(text, W_t, b_t, p_et, n, DT);
    gemm_n128<true, true, false><<<gm, 256>>>(vis,  W_v, b_v, p_ev, n, DV);

    // --- GCN layer 0: t0 = concat(et,ev) @ W_mp0 (split K), then aggregate ---
    gemm_n128<false, false, false><<<gm, 256>>>(p_et, W_mp0,            nullptr, p_t, n, DE);
    gemm_n128<false, false, true ><<<gm, 256>>>(p_ev, W_mp0 + 128 * 128, nullptr, p_t, n, DE);
    {
        int warps_per_block = 8;
        int blocks = (n + warps_per_block - 1) / warps_per_block;
        aggregate_kernel<<<blocks, 256>>>(p_t, b_mp0, p_h, n);
    }

    // --- GCN layer 1 ---
    gemm_n128<false, false, false><<<gm, 256>>>(p_h, W_mp1, nullptr, p_t, n, DE);
    {
        int warps_per_block = 8;
        int blocks = (n + warps_per_block - 1) / warps_per_block;
        aggregate_kernel<<<blocks, 256>>>(p_t, b_mp1, p_h, n);
    }

    // --- heads + final average ---
    size_t smem_heads = 3 * 5120 * sizeof(float);   // 61440 B
    cudaFuncSetAttribute(heads_kernel, cudaFuncAttributeMaxDynamicSharedMemorySize,
                         (int)smem_heads);
    heads_kernel<<<1184, 256, smem_heads>>>(p_et, p_ev, p_h,
                                            W_c, b_c, W_ut, b_ut, W_uv, b_uv,
                                            out, n);
}

// round 14
// speedup vs baseline: 1.3969x; 1.3969x over previous
#include <cuda_runtime.h>
#include <cuda_bf16.h>
#include <cstdint>

// ---------------------------------------------------------------------------
// Problem constants
// ---------------------------------------------------------------------------
#define NN 100000
#define EE 1600000
#define DT 768
#define DV 512
#define DE 128
#define NC 40

#define KT_TOTAL 1664   // 768 + 512 + 256 + 128  (concatenated weight K)
#define KOFF_T   0
#define KOFF_V   768
#define KOFF_M0  1280
#define KOFF_M1  1536

// ---------------------------------------------------------------------------
// Scratch (device globals — no allocation allowed)
// ---------------------------------------------------------------------------
__device__ float g_et[(size_t)NN * DE];
__device__ float g_ev[(size_t)NN * DE];
__device__ float g_t [(size_t)NN * DE];
__device__ float g_h [(size_t)NN * DE];
__device__ int   g_deg_in [NN];
__device__ int   g_deg_out[NN];
__device__ int   g_row    [NN];
__device__ int   g_cursor [NN];
__device__ int   g_bsum   [128];
__device__ float g_inv_in [NN];
__device__ float g_inv_out[NN];
__device__ int   g_csr_src[EE];
__device__ float g_csr_w  [EE];
// weights, transposed to [N=128][K] and split to bf16 hi/lo
__device__ __nv_bfloat16 g_WbH[(size_t)128 * KT_TOTAL];
__device__ __nv_bfloat16 g_WbL[(size_t)128 * KT_TOTAL];

// ---------------------------------------------------------------------------
// PTX helpers (sm_80-era features only — the toolchain targets compute_103,
// which gates out all 'a'-suffix (tcgen05/TMEM) instructions)
// ---------------------------------------------------------------------------
__device__ __forceinline__ uint32_t smem_u32(const void* p) {
    uint32_t a;
    asm("{ .reg .u64 t; cvta.to.shared.u64 t, %1; cvt.u32.u64 %0, t; }" : "=r"(a) : "l"(p));
    return a;
}
__device__ __forceinline__ uint64_t gaddr(const void* p) {
    uint64_t a;
    asm("cvta.to.global.u64 %0, %1;" : "=l"(a) : "l"(p));
    return a;
}
#define CP_ASYNC16(dst, src) \
    asm volatile("cp.async.cg.shared.global [%0], [%1], 16;" :: "r"(dst), "l"(src))
#define CP_COMMIT() asm volatile("cp.async.commit_group;" ::: "memory")
#define CP_WAIT0()  asm volatile("cp.async.wait_group 0;" ::: "memory")

__device__ __forceinline__ void ldsm4(uint32_t* r, uint32_t addr) {
    asm volatile("ldmatrix.sync.aligned.m8n8.x4.shared.b16 {%0,%1,%2,%3}, [%4];"
        : "=r"(r[0]), "=r"(r[1]), "=r"(r[2]), "=r"(r[3]) : "r"(addr));
}
__device__ __forceinline__ void mma16816(float* d, const uint32_t* a, const uint32_t* b) {
    asm volatile("mma.sync.aligned.m16n8k16.row.col.f32.bf16.bf16.f32 "
        "{%0,%1,%2,%3}, {%4,%5,%6,%7}, {%8,%9}, {%0,%1,%2,%3};"
        : "+f"(d[0]), "+f"(d[1]), "+f"(d[2]), "+f"(d[3])
        : "r"(a[0]), "r"(a[1]), "r"(a[2]), "r"(a[3]), "r"(b[0]), "r"(b[1]));
}

// ---------------------------------------------------------------------------
// Degree / CSR kernels (unchanged)
// ---------------------------------------------------------------------------
__global__ void zero3_kernel(int n) {
    int i = blockIdx.x * blockDim.x + threadIdx.x;
    if (i < n) { g_deg_in[i] = 0; g_deg_out[i] = 0; g_cursor[i] = 0; }
}
__global__ void hist_kernel(const int* __restrict__ src, const int* __restrict__ dst, int e) {
    int i = blockIdx.x * blockDim.x + threadIdx.x;
    if (i < e) { atomicAdd(&g_deg_out[src[i]], 1); atomicAdd(&g_deg_in[dst[i]], 1); }
}
__global__ void inv_kernel(int n) {
    int i = blockIdx.x * blockDim.x + threadIdx.x;
    if (i < n) {
        int dout = g_deg_out[i]; if (dout < 1) dout = 1;
        int din  = g_deg_in [i]; if (din  < 1) din  = 1;
        g_inv_out[i] = rsqrtf((float)dout);
        g_inv_in [i] = rsqrtf((float)din);
    }
}
__global__ void scan_local(int n) {
    __shared__ int s[1024];
    int t = threadIdx.x;
    int gid = blockIdx.x * 1024 + t;
    int v = (gid < n) ? g_deg_in[gid] : 0;
    s[t] = v; __syncthreads();
    for (int off = 1; off < 1024; off <<= 1) {
        int x = (t >= off) ? s[t - off] : 0;
        __syncthreads(); s[t] += x; __syncthreads();
    }
    if (gid < n) g_row[gid] = s[t] - v;
    if (t == 1023) g_bsum[blockIdx.x] = s[1023];
}
__global__ void scan_bsums(int nb) {
    if (blockIdx.x == 0 && threadIdx.x == 0) {
        int run = 0;
        for (int i = 0; i < nb; i++) { int v = g_bsum[i]; g_bsum[i] = run; run += v; }
    }
}
__global__ void scan_add(int n) {
    int gid = blockIdx.x * blockDim.x + threadIdx.x;
    if (gid < n) g_row[gid] += g_bsum[gid >> 10];
}
__global__ void scatter_kernel(const int* __restrict__ src, const int* __restrict__ dst, int e) {
    int i = blockIdx.x * blockDim.x + threadIdx.x;
    if (i < e) {
        int s = src[i], d = dst[i];
        int pos = atomicAdd(&g_cursor[d], 1);
        int idx = g_row[d] + pos;
        g_csr_src[idx] = s;
        g_csr_w[idx]   = g_inv_out[s] * g_inv_in[d];
    }
}

// ---------------------------------------------------------------------------
// Weight preconversion: W [K][128] fp32  ->  g_WbH/g_WbL [128][KT_TOTAL] bf16
// ---------------------------------------------------------------------------
__global__ void wconv_kernel(const float* __restrict__ W, int K, int koff) {
    int i = blockIdx.x * blockDim.x + threadIdx.x;
    if (i >= K * 128) return;
    int k = i >> 7, n = i & 127;
    float x = W[(size_t)k * 128 + n];
    __nv_bfloat16 hi = __float2bfloat16_rn(x);
    __nv_bfloat16 lo = __float2bfloat16_rn(x - __bfloat162float(hi));
    size_t d = (size_t)n * KT_TOTAL + koff + k;
    g_WbH[d] = hi;
    g_WbL[d] = lo;
}

// ---------------------------------------------------------------------------
// bf16 split-precision GEMM via mma.sync: C[M x 128] = A[M x K] @ W[K x 128]
// A given as (A0, K0) optionally concat (A1, K1).  BK=64, double-buffered.
// 8 warps: warp (wm, wn) computes rows [wm*32,+32) x cols [wn*64,+64).
// ---------------------------------------------------------------------------
#define BK      64
#define PADK    72                    // bf16 row stride (144 B = 9 x 16B)
#define ROWB    (PADK * 2)            // 144 bytes
#define TILE_B  (128 * ROWB)          // 18432 B per matrix tile
#define OFF_AHI 0
#define OFF_ALO (1 * TILE_B)
#define OFF_BHI (2 * TILE_B)
#define OFF_BLO (3 * TILE_B)
#define STAGE   (4 * TILE_B)          // 73728 B
#define SMEM_GEMM (2 * STAGE)         // 147456 B

template <bool RELU, bool BIAS>
__global__ __launch_bounds__(256, 1)
void gemm_mma(const float* __restrict__ A0, int lda0, int K0,
              const float* __restrict__ A1, int lda1, int K1,
              int koffW, const float* __restrict__ bias,
              float* __restrict__ C, int M) {
    extern __shared__ char smem[];
    const uint32_t sb = smem_u32(smem);

    const int tid  = threadIdx.x;
    const int lane = tid & 31;
    const int wid  = tid >> 5;
    const int wm   = wid & 3;          // M quadrant (32 rows)
    const int wn   = wid >> 2;         // N half (64 cols)
    const int rowBase = blockIdx.x * 128;
    const int Ktot = K0 + K1;
    const int nc   = Ktot >> 6;

    // A load mapping: 2 threads per row, 8 float4 each
    const int arow = tid >> 1;
    const int aq0  = (tid & 1) * 8;
    const bool arow_ok = (rowBase + arow) < M;
    // B load mapping: 2 threads per n-row, 4 uint4 each (x2 for hi/lo)
    const int brow = tid >> 1;
    const int bu0  = (tid & 1) * 4;

    const uint64_t WbH = gaddr((const void*)g_WbH);
    const uint64_t WbL = gaddr((const void*)g_WbL);

    auto issueB = [&](int kb, int stage) {
        uint64_t srcH = WbH + (uint64_t)((size_t)brow * KT_TOTAL + koffW + kb) * 2;
        uint64_t srcL = WbL + (uint64_t)((size_t)brow * KT_TOTAL + koffW + kb) * 2;
        uint32_t dbase = sb + stage * STAGE + (uint32_t)(brow * ROWB);
#pragma unroll
        for (int j = 0; j < 4; j++) {
            int u = bu0 + j;
            CP_ASYNC16(dbase + OFF_BHI + u * 16, srcH + u * 16);
            CP_ASYNC16(dbase + OFF_BLO + u * 16, srcL + u * 16);
        }
    };

    auto ldgA = [&](int kb, float4* av) {
        const float* Ap; int lda, kcol;
        if (kb < K0) { Ap = A0; lda = lda0; kcol = kb; }
        else         { Ap = A1; lda = lda1; kcol = kb - K0; }
        const float* rp = Ap + (size_t)(rowBase + arow) * lda + kcol;
#pragma unroll
        for (int j = 0; j < 8; j++) {
            int q = aq0 + j;
            av[j] = arow_ok ? __ldg((const float4*)(rp + q * 4))
                            : make_float4(0.f, 0.f, 0.f, 0.f);
        }
    };

    auto stsA = [&](int stage, const float4* av) {
        char* st = smem + stage * STAGE;
#pragma unroll
        for (int j = 0; j < 8; j++) {
            int q = aq0 + j;
            float4 v = av[j];
            __nv_bfloat16 h0 = __float2bfloat16_rn(v.x);
            __nv_bfloat16 h1 = __float2bfloat16_rn(v.y);
            __nv_bfloat16 h2 = __float2bfloat16_rn(v.z);
            __nv_bfloat16 h3 = __float2bfloat16_rn(v.w);
            __nv_bfloat16 l0 = __float2bfloat16_rn(v.x - __bfloat162float(h0));
            __nv_bfloat16 l1 = __float2bfloat16_rn(v.y - __bfloat162float(h1));
            __nv_bfloat16 l2 = __float2bfloat16_rn(v.z - __bfloat162float(h2));
            __nv_bfloat16 l3 = __float2bfloat16_rn(v.w - __bfloat162float(h3));
            uint32_t hA = ((uint32_t)__bfloat16_as_ushort(h1) << 16) | __bfloat16_as_ushort(h0);
            uint32_t hB = ((uint32_t)__bfloat16_as_ushort(h3) << 16) | __bfloat16_as_ushort(h2);
            uint32_t lA = ((uint32_t)__bfloat16_as_ushort(l1) << 16) | __bfloat16_as_ushort(l0);
            uint32_t lB = ((uint32_t)__bfloat16_as_ushort(l3) << 16) | __bfloat16_as_ushort(l2);
            uint32_t off = (uint32_t)(arow * ROWB + q * 8);
            *(uint2*)(st + OFF_AHI + off) = make_uint2(hA, hB);
            *(uint2*)(st + OFF_ALO + off) = make_uint2(lA, lB);
        }
    };

    float acc[2][8][4];
#pragma unroll
    for (int f = 0; f < 2; f++)
#pragma unroll
        for (int nf = 0; nf < 8; nf++)
#pragma unroll
            for (int j = 0; j < 4; j++) acc[f][nf][j] = 0.f;

    auto compute = [&](int stage) {
        uint32_t st = sb + stage * STAGE;
#pragma unroll
        for (int ks = 0; ks < 4; ks++) {
            uint32_t aH[2][4], aL[2][4];
#pragma unroll
            for (int f = 0; f < 2; f++) {
                uint32_t ra = st + OFF_AHI
                    + (uint32_t)((wm * 32 + f * 16 + (lane & 15)) * ROWB
                                 + (ks * 16 + (lane >> 4) * 8) * 2);
                ldsm4(aH[f], ra);
                ldsm4(aL[f], ra + (OFF_ALO - OFF_AHI));
            }
            uint32_t bH[4][4], bL[4][4];
            const int mi = lane >> 3;
#pragma unroll
            for (int np = 0; np < 4; np++) {
                uint32_t rb = st + OFF_BHI
                    + (uint32_t)((wn * 64 + np * 16 + (mi >> 1) * 8 + (lane & 7)) * ROWB
                                 + (ks * 16 + (mi & 1) * 8) * 2);
                ldsm4(bH[np], rb);
                ldsm4(bL[np], rb + (OFF_BLO - OFF_BHI));
            }
#pragma unroll
            for (int np = 0; np < 4; np++)
#pragma unroll
                for (int f = 0; f < 2; f++) {
                    mma16816(acc[f][2 * np],     aH[f], bH[np]);
                    mma16816(acc[f][2 * np + 1], aH[f], bH[np] + 2);
                    mma16816(acc[f][2 * np],     aH[f], bL[np]);
                    mma16816(acc[f][2 * np + 1], aH[f], bL[np] + 2);
                    mma16816(acc[f][2 * np],     aL[f], bH[np]);
                    mma16816(acc[f][2 * np + 1], aL[f], bH[np] + 2);
                }
        }
    };

    // ---- prologue: stage chunk 0 ----
    issueB(0, 0);
    CP_COMMIT();
    {
        float4 av0[8];
        ldgA(0, av0);
        stsA(0, av0);
    }
    CP_WAIT0();
    __syncthreads();

    // ---- main pipeline ----
    float4 av[8];
    for (int c = 0; c < nc; c++) {
        int b = c & 1;
        bool more = (c + 1) < nc;
        if (more) {
            issueB((c + 1) * BK, b ^ 1);
            CP_COMMIT();
            ldgA((c + 1) * BK, av);
        }
        compute(b);
        if (more) {
            stsA(b ^ 1, av);
            CP_WAIT0();
            __syncthreads();
        }
    }

    // ---- epilogue ----
#pragma unroll
    for (int f = 0; f < 2; f++) {
#pragma unroll
        for (int nf = 0; nf < 8; nf++) {
            int n = wn * 64 + nf * 8 + (lane & 3) * 2;
            float b0 = 0.f, b1 = 0.f;
            if (BIAS) { b0 = __ldg(bias + n); b1 = __ldg(bias + n + 1); }
            int m0 = rowBase + wm * 32 + f * 16 + (lane >> 2);
            int m1 = m0 + 8;
            float v0 = acc[f][nf][0] + b0, v1 = acc[f][nf][1] + b1;
            float v2 = acc[f][nf][2] + b0, v3 = acc[f][nf][3] + b1;
            if (RELU) {
                v0 = fmaxf(v0, 0.f); v1 = fmaxf(v1, 0.f);
                v2 = fmaxf(v2, 0.f); v3 = fmaxf(v3, 0.f);
            }
            if (m0 < M) *(float2*)(C + (size_t)m0 * 128 + n) = make_float2(v0, v1);
            if (m1 < M) *(float2*)(C + (size_t)m1 * 128 + n) = make_float2(v2, v3);
        }
    }
}

// ---------------------------------------------------------------------------
// Edge aggregation (unchanged)
// ---------------------------------------------------------------------------
__global__ void aggregate_kernel(const float* __restrict__ t, const float* __restrict__ bias,
                                 float* __restrict__ out, int n) {
    int warp = (blockIdx.x * blockDim.x + threadIdx.x) >> 5;
    int lane = threadIdx.x & 31;
    if (warp >= n) return;
    int start = g_row[warp];
    int cnt   = g_deg_in[warp];
    const int c = lane * 4;
    float4 acc = make_float4(0.f, 0.f, 0.f, 0.f);
    int i = 0;
    for (; i + 1 < cnt; i += 2) {
        int   s0 = g_csr_src[start + i];
        float w0 = g_csr_w  [start + i];
        int   s1 = g_csr_src[start + i + 1];
        float w1 = g_csr_w  [start + i + 1];
        float4 v0 = *(const float4*)(t + (size_t)s0 * 128 + c);
        float4 v1 = *(const float4*)(t + (size_t)s1 * 128 + c);
        acc.x += w0 * v0.x; acc.y += w0 * v0.y; acc.z += w0 * v0.z; acc.w += w0 * v0.w;
        acc.x += w1 * v1.x; acc.y += w1 * v1.y; acc.z += w1 * v1.z; acc.w += w1 * v1.w;
    }
    for (; i < cnt; i++) {
        int   s = g_csr_src[start + i];
        float w = g_csr_w  [start + i];
        float4 v = *(const float4*)(t + (size_t)s * 128 + c);
        acc.x += w * v.x; acc.y += w * v.y; acc.z += w * v.z; acc.w += w * v.w;
    }
    float4 b = *(const float4*)(bias + c);
    acc.x += b.x; acc.y += b.y; acc.z += b.z; acc.w += b.w;
    *(float4*)(out + (size_t)warp * 128 + c) = acc;
}

// ---------------------------------------------------------------------------
// Heads (unchanged)
// ---------------------------------------------------------------------------
__global__ void heads_kernel(const float* __restrict__ et, const float* __restrict__ ev,
                             const float* __restrict__ h,
                             const float* __restrict__ Wc, const float* __restrict__ bc,
                             const float* __restrict__ Wt, const float* __restrict__ bt,
                             const float* __restrict__ Wv, const float* __restrict__ bv,
                             float* __restrict__ out, int n) {
    extern __shared__ float sw[];
    float* sWc = sw;
    float* sWt = sw + 5120;
    float* sWv = sw + 10240;
    for (int i = threadIdx.x; i < 5120; i += blockDim.x) {
        sWc[i] = Wc[i]; sWt[i] = Wt[i]; sWv[i] = Wv[i];
    }
    __syncthreads();

    int warp   = (blockIdx.x * blockDim.x + threadIdx.x) >> 5;
    int lane   = threadIdx.x & 31;
    int nwarps = (gridDim.x * blockDim.x) >> 5;
    bool s2 = lane < 8;
    int col1 = lane, col2 = 32 + lane;
    size_t MO = (size_t)n * 40;

    for (int node = warp; node < n; node += nwarps) {
        const float* xt = et + (size_t)node * 128;
        const float* xv = ev + (size_t)node * 128;
        const float* xh = h  + (size_t)node * 128;
        float c0 = 0.f, c1 = 0.f, t0 = 0.f, t1 = 0.f, v0 = 0.f, v1 = 0.f;
#pragma unroll 4
        for (int k = 0; k < 128; k++) {
            float a = xh[k], b = xt[k], c = xv[k];
            c0 += a * sWc[k * 40 + col1];
            t0 += b * sWt[k * 40 + col1];
            v0 += c * sWv[k * 40 + col1];
            if (s2) {
                c1 += a * sWc[k * 40 + col2];
                t1 += b * sWt[k * 40 + col2];
                v1 += c * sWv[k * 40 + col2];
            }
        }
        c0 += bc[col1]; t0 += bt[col1]; v0 += bv[col1];
        float f0 = (c0 + t0 + v0) * (1.f / 3.f);
        size_t base = (size_t)node * 40;
        out[base + col1]          = f0;
        out[MO + base + col1]     = c0;
        out[2 * MO + base + col1] = t0;
        out[3 * MO + base + col1] = v0;
        if (s2) {
            c1 += bc[col2]; t1 += bt[col2]; v1 += bv[col2];
            float f1 = (c1 + t1 + v1) * (1.f / 3.f);
            out[base + col2]          = f1;
            out[MO + base + col2]     = c1;
            out[2 * MO + base + col2] = t1;
            out[3 * MO + base + col2] = v1;
        }
    }
}

// ---------------------------------------------------------------------------
// Launch
// ---------------------------------------------------------------------------
extern "C" void kernel_launch(void* const* d_in, const int* in_sizes, int n_in,
                              void* d_out, int out_size) {
    const float* text = (const float*)d_in[0];
    const float* vis  = (const float*)d_in[1];
    const int* esrc   = (const int*)d_in[2];
    const int* edst   = (const int*)d_in[3];
    const float* W_t  = (const float*)d_in[4];
    const float* b_t  = (const float*)d_in[5];
    const float* W_v  = (const float*)d_in[6];
    const float* b_v  = (const float*)d_in[7];
    const float* W_mp0 = (const float*)d_in[8];
    const float* b_mp0 = (const float*)d_in[9];
    const float* W_mp1 = (const float*)d_in[10];
    const float* b_mp1 = (const float*)d_in[11];
    const float* W_c  = (const float*)d_in[12];
    const float* b_c  = (const float*)d_in[13];
    const float* W_ut = (const float*)d_in[14];
    const float* b_ut = (const float*)d_in[15];
    const float* W_uv = (const float*)d_in[16];
    const float* b_uv = (const float*)d_in[17];
    float* out = (float*)d_out;

    int n = in_sizes[0] / DT;
    int e = in_sizes[2];

    float *p_et, *p_ev, *p_t, *p_h;
    cudaGetSymbolAddress((void**)&p_et, g_et);
    cudaGetSymbolAddress((void**)&p_ev, g_ev);
    cudaGetSymbolAddress((void**)&p_t,  g_t);
    cudaGetSymbolAddress((void**)&p_h,  g_h);

    int nb_n = (n + 255) / 256;
    int nb_e = (e + 255) / 256;
    int nb_scan = (n + 1023) / 1024;

    // --- graph prep ---
    zero3_kernel<<<nb_n, 256>>>(n);
    hist_kernel<<<nb_e, 256>>>(esrc, edst, e);
    inv_kernel<<<nb_n, 256>>>(n);
    scan_local<<<nb_scan, 1024>>>(n);
    scan_bsums<<<1, 32>>>(nb_scan);
    scan_add<<<nb_n, 256>>>(n);
    scatter_kernel<<<nb_e, 256>>>(esrc, edst, e);

    // --- weight preconversion (transpose + bf16 hi/lo split) ---
    wconv_kernel<<<(DT * 128 + 255) / 256, 256>>>(W_t,  DT,     KOFF_T);
    wconv_kernel<<<(DV * 128 + 255) / 256, 256>>>(W_v,  DV,     KOFF_V);
    wconv_kernel<<<(256 * 128 + 255) / 256, 256>>>(W_mp0, 256,  KOFF_M0);
    wconv_kernel<<<(128 * 128 + 255) / 256, 256>>>(W_mp1, 128,  KOFF_M1);

    // --- tensor-core GEMMs (mma.sync bf16 hi/lo split) ---
    cudaFuncSetAttribute(gemm_mma<true, true>,
                         cudaFuncAttributeMaxDynamicSharedMemorySize, SMEM_GEMM);
    cudaFuncSetAttribute(gemm_mma<false, false>,
                         cudaFuncAttributeMaxDynamicSharedMemorySize, SMEM_GEMM);
    int gm = (n + 127) / 128;

    // encoders: relu(x @ W + b)
    gemm_mma<true, true><<<gm, 256, SMEM_GEMM>>>(text, DT, DT, nullptr, 0, 0,
                                                 KOFF_T, b_t, p_et, n);
    gemm_mma<true, true><<<gm, 256, SMEM_GEMM>>>(vis, DV, DV, nullptr, 0, 0,
                                                 KOFF_V, b_v, p_ev, n);

    // GCN layer 0: concat(et, ev) @ W_mp0 as one K=256 GEMM, then aggregate
    gemm_mma<false, false><<<gm, 256, SMEM_GEMM>>>(p_et, DE, DE, p_ev, DE, DE,
                                                   KOFF_M0, nullptr, p_t, n);
    aggregate_kernel<<<(n + 7) / 8, 256>>>(p_t, b_mp0, p_h, n);

    // GCN layer 1
    gemm_mma<false, false><<<gm, 256, SMEM_GEMM>>>(p_h, DE, DE, nullptr, 0, 0,
                                                   KOFF_M1, nullptr, p_t, n);
    aggregate_kernel<<<(n + 7) / 8, 256>>>(p_t, b_mp1, p_h, n);

    // --- heads ---
    size_t smem_heads = 3 * 5120 * sizeof(float);
    cudaFuncSetAttribute(heads_kernel, cudaFuncAttributeMaxDynamicSharedMemorySize,
                         (int)smem_heads);
    heads_kernel<<<1184, 256, smem_heads>>>(p_et, p_ev, p_h,
                                            W_c, b_c, W_ut, b_ut, W_uv, b_uv,
                                            out, n);
}